// round 11
// baseline (speedup 1.0000x reference)
#include <cuda_runtime.h>
#include <cuda_fp16.h>

// FP_14396730376440 — fan-beam forward projection, geometry recomputed on-GPU.
// R9: image stored as fp16 quad cells (v00,v10,v01,v11 = 8 bytes) in a tiled
// layout (8x4 cells = one 128B line), making a warp's compact tap-arc touch
// ~4-8 cache lines regardless of orientation (was up to 32 for vertical arcs).

#define ND 368
#define NV 180
#define NRAYS (ND * NV)
#define IMG_W 256
#define IMG_H 256
#define PAD 2
#define GW 264                 // padded grid dim (multiple of 8 and 4)
#define TILES_X (GW / 8)       // 33
#define NCELLS (GW * GW)
#define NCHUNK 8
#define F_INF __int_as_float(0x7f800000)

// ---------------- static device scratch ----------------
// cell (cx,cy), cx=x0+PAD, cy=y0+PAD: uint2 = (half2(v00,v10), half2(v01,v11))
__device__ uint2  d_img_tile[NCELLS];
__device__ float4 d_rayA[NRAYS];   // invx, offx, invy, offy
__device__ float4 d_rayB[NRAYS];   // fDx, fsx, fDy, fsy   (sample-pos affine)
__device__ float4 d_rayC[NRAYS];   // lo, hi, Dx, Dy
__device__ float  d_rayS[NRAYS];   // s2d

#define PAD_BLOCKS ((NCELLS + 255) / 256)
#define RAY_BLOCKS ((NRAYS + 255) / 256)

__device__ __forceinline__ int tile_idx(int cx, int cy)
{
    // tile = (cx>>3, cy>>2); within-tile = (cx&7, cy&3); 32 cells per tile
    return (((cy >> 2) * TILES_X + (cx >> 3)) << 5) + ((cy & 3) << 3) + (cx & 7);
}

// ---------------- K1: fused tile-pack + per-ray setup (pure f32) ----------------
__global__ void setup_kernel(const float* __restrict__ img)
{
    if (blockIdx.x < PAD_BLOCKS) {
        int idx = blockIdx.x * 256 + threadIdx.x;
        if (idx >= NCELLS) return;
        int cy = idx / GW, cx = idx % GW;
        auto px = [&](int xx, int yy) -> float {
            int ix = xx - PAD, iy = yy - PAD;
            if ((unsigned)ix < (unsigned)IMG_W && (unsigned)iy < (unsigned)IMG_H)
                return img[iy * IMG_W + ix];
            return 0.0f;
        };
        __half2 t = __floats2half2_rn(px(cx, cy),     px(cx + 1, cy));
        __half2 b = __floats2half2_rn(px(cx, cy + 1), px(cx + 1, cy + 1));
        uint2 cell;
        cell.x = *reinterpret_cast<unsigned*>(&t);
        cell.y = *reinterpret_cast<unsigned*>(&b);
        d_img_tile[tile_idx(cx, cy)] = cell;
        return;
    }

    int q = (blockIdx.x - PAD_BLOCKS) * 256 + threadIdx.x;
    if (q >= NRAYS) return;
    int v = q / ND;
    int d = q - v * ND;

    float sb, cb;
    sincospif((float)v / 90.0f, &sb, &cb);        // beta = v * 2*pi/180
    float rdy = 2.0f * (float)d - 367.0f;
    float sx = -500.0f * cb, sy = 500.0f * sb;
    float Dx = fmaf(sb, rdy, 500.0f * cb) - sx;
    float Dy = fmaf(cb, rdy, -500.0f * sb) - sy;
    float cx = -128.0f - sx, cy = -128.0f - sy;
    float invx = 1.0f / Dx, invy = 1.0f / Dy;
    float offx = cx * invx, offy = cy * invy;

    // Window endpoints in the SAME fmaf form the merge loop uses.
    float ex0 = offx, ex1 = fmaf(256.0f, invx, offx);
    float ey0 = offy, ey1 = fmaf(256.0f, invy, offy);
    float lo = fmaxf(fmaxf(fminf(ex0, ex1), fminf(ey0, ey1)), 0.0f);
    float hi = fminf(fminf(fmaxf(ex0, ex1), fmaxf(ey0, ey1)), 1.0f);

    const float scale = 128.0f / 127.5f;
    d_rayA[q] = make_float4(invx, offx, invy, offy);
    d_rayB[q] = make_float4(Dx * scale, fmaf(sx, scale, 127.5f),
                            Dy * scale, fmaf(sy, scale, 127.5f));
    d_rayC[q] = make_float4(lo, hi, Dx, Dy);
    d_rayS[q] = sqrtf(fmaf(Dx, Dx, Dy * Dy));
}

// find first crossing (ascending order) with value >= clo
__device__ __forceinline__ void init_family(float clo, float Df, float inv,
                                            float off, float dirf,
                                            float& kf, float& val)
{
    float k = rintf((clo - off) * Df);
    k = fminf(fmaxf(k, -2.0f), 258.0f);
    #pragma unroll
    for (int i = 0; i < 4; ++i) {
        float vc = fmaf(k, inv, off);
        if (vc < clo)                                k += dirf;
        else if (fmaf(k - dirf, inv, off) >= clo)    k -= dirf;
        else break;
    }
    kf = k;
    val = fmaf(k, inv, off);
}

// ---------------- K2: main kernel ----------------
// Block = 256 threads = 32 adjacent rays x 8 chunk-warps.
__global__ __launch_bounds__(256)
void fp_kernel(float* __restrict__ out)
{
    __shared__ float s_part[NCHUNK][32];

    const int lane  = threadIdx.x & 31;
    const int chunk = threadIdx.x >> 5;
    const int q     = blockIdx.x * 32 + lane;   // 2070 * 32 = NRAYS exactly

    const float4 A = d_rayA[q];
    const float4 B = d_rayB[q];
    const float4 C = d_rayC[q];
    const float invx = A.x, offx = A.y, invy = A.z, offy = A.w;
    const float fDx = B.x, fsx = B.y, fDy = B.z, fsy = B.w;
    const float lo = C.x, hi = C.y, Dx = C.z, Dy = C.w;
    const float dirx = (invx > 0.0f) ? 1.0f : -1.0f;
    const float diry = (invy > 0.0f) ? 1.0f : -1.0f;

    // chunk owns intervals starting in [clo, limit)
    const float w8 = (hi - lo) * 0.125f;
    const float clo = fmaf((float)chunk, w8, lo);
    const float limit = (chunk == 7) ? F_INF : fmaf((float)(chunk + 1), w8, lo);

    float kx, vx, ky, vy;
    init_family(clo, Dx, invx, offx, dirx, kx, vx);
    init_family(clo, Dy, invy, offy, diry, ky, vy);

    float acc = 0.0f;
    float cprev = fminf(vx, vy);
    if (vx <= vy) { kx += dirx; vx = fmaf(kx, invx, offx); }
    else          { ky += diry; vy = fmaf(ky, invy, offy); }

    #pragma unroll 1
    while (cprev < limit) {
        const float nxt = fminf(vx, vy);
        if (nxt > hi) break;

        const float w   = nxt - cprev;
        const float mid = fmaf(0.5f, w, cprev);
        const float ix  = fmaf(mid, fDx, fsx);
        const float iy  = fmaf(mid, fDy, fsy);
        const float x0f = floorf(ix);
        const float y0f = floorf(iy);
        const float fx  = ix - x0f;
        const float fy  = iy - y0f;
        const int cxi   = __float2int_rn(x0f) + PAD;
        const int cyi   = __float2int_rn(y0f) + PAD;

        const uint2 cell = __ldg(&d_img_tile[tile_idx(cxi, cyi)]);
        const float2 t = __half22float2(*reinterpret_cast<const __half2*>(&cell.x));
        const float2 b = __half22float2(*reinterpret_cast<const __half2*>(&cell.y));
        const float top = fmaf(fx, t.y - t.x, t.x);
        const float bot = fmaf(fx, b.y - b.x, b.x);
        acc = fmaf(w, fmaf(fy, bot - top, top), acc);

        if (vx <= vy) { kx += dirx; vx = fmaf(kx, invx, offx); }
        else          { ky += diry; vy = fmaf(ky, invy, offy); }
        cprev = nxt;
    }

    // combine 8 chunk partials per ray through shared memory
    s_part[chunk][lane] = acc;
    __syncthreads();

    if (chunk == 0) {
        float total = 0.0f;
        #pragma unroll
        for (int c = 0; c < NCHUNK; ++c)
            total += s_part[c][lane];

        const int v = q / ND;
        const int d = q - v * ND;
        out[d * NV + v] = d_rayS[q] * total;
    }
}

extern "C" void kernel_launch(void* const* d_in, const int* in_sizes, int n_in,
                              void* d_out, int out_size)
{
    const float* img = (const float*)d_in[0];
    float* out = (float*)d_out;

    setup_kernel<<<PAD_BLOCKS + RAY_BLOCKS, 256>>>(img);
    fp_kernel<<<NRAYS / 32, 256>>>(out);
}